// round 16
// baseline (speedup 1.0000x reference)
#include <cuda_runtime.h>
#include <cuda_fp16.h>
#include <math.h>
#include <stdint.h>

// Problem constants
#define Bq  2
#define Sq  2048
#define Dm  1024
#define Hh  16
#define HDc 64
#define Mtot (Bq*Sq)   // 4096

// ---------------- device scratch (fp16) ----------------
__device__ __half g_Xf[Mtot*Dm];                  // x single fp16
__device__ __half g_Wf[4][Dm*Dm];                 // W^T single fp16, [N][K]
__device__ __half g_Qf[Mtot*Dm];                  // Q single, pre-scaled 0.125*log2e
__device__ __half g_Kf[Mtot*Dm], g_Vf[Mtot*Dm];   // K/V single
__device__ __half g_AH[Mtot*Dm];                  // attention out single fp16

// ---------------- helpers ----------------
__device__ __forceinline__ uint32_t smem_u32(const void* p) {
    uint32_t a;
    asm("{ .reg .u64 t; cvta.to.shared.u64 t, %1; cvt.u32.u64 %0, t; }" : "=r"(a) : "l"(p));
    return a;
}
__device__ __forceinline__ void cp16(uint32_t saddr, const void* gptr) {
    asm volatile("cp.async.cg.shared.global [%0], [%1], 16;" :: "r"(saddr), "l"(gptr) : "memory");
}
__device__ __forceinline__ void cp_commit() {
    asm volatile("cp.async.commit_group;" ::: "memory");
}
__device__ __forceinline__ void cp_wait0() {
    asm volatile("cp.async.wait_group 0;" ::: "memory");
}
__device__ __forceinline__ void ldsm_x4(uint32_t* r, uint32_t a) {
    asm volatile("ldmatrix.sync.aligned.m8n8.x4.shared.b16 {%0,%1,%2,%3}, [%4];"
                 : "=r"(r[0]), "=r"(r[1]), "=r"(r[2]), "=r"(r[3]) : "r"(a));
}
__device__ __forceinline__ void ldsm_x2(uint32_t* r, uint32_t a) {
    asm volatile("ldmatrix.sync.aligned.m8n8.x2.shared.b16 {%0,%1}, [%2];"
                 : "=r"(r[0]), "=r"(r[1]) : "r"(a));
}
__device__ __forceinline__ void ldsm_x2t(uint32_t* r, uint32_t a) {
    asm volatile("ldmatrix.sync.aligned.m8n8.x2.trans.shared.b16 {%0,%1}, [%2];"
                 : "=r"(r[0]), "=r"(r[1]) : "r"(a));
}
__device__ __forceinline__ void mma16816(float* c, const uint32_t* a, const uint32_t* b) {
    asm volatile(
        "mma.sync.aligned.m16n8k16.row.col.f32.f16.f16.f32 "
        "{%0,%1,%2,%3}, {%4,%5,%6,%7}, {%8,%9}, {%0,%1,%2,%3};"
        : "+f"(c[0]), "+f"(c[1]), "+f"(c[2]), "+f"(c[3])
        : "r"(a[0]), "r"(a[1]), "r"(a[2]), "r"(a[3]), "r"(b[0]), "r"(b[1]));
}
__device__ __forceinline__ uint32_t ex2h2(uint32_t x) {
    uint32_t y;
    asm("ex2.approx.f16x2 %0, %1;" : "=r"(y) : "r"(x));
    return y;
}
__device__ __forceinline__ uint32_t hmax2(uint32_t a, uint32_t b) {
    uint32_t y;
    asm("max.f16x2 %0, %1, %2;" : "=r"(y) : "r"(a), "r"(b));
    return y;
}
__device__ __forceinline__ uint32_t h2pack(float a, float b) {
    __half2 h = __floats2half2_rn(a, b);
    return *(uint32_t*)&h;
}

// ---------------------------------------------------------------------------
// conversion kernels
// ---------------------------------------------------------------------------
__global__ __launch_bounds__(256) void convx_k(const float* __restrict__ X,
                                               __half* __restrict__ H)
{
    int i = blockIdx.x * blockDim.x + threadIdx.x;
    float4 v = ((const float4*)X)[i];
    ((uint2*)H)[i] = make_uint2(h2pack(v.x, v.y), h2pack(v.z, v.w));
}

__global__ __launch_bounds__(256) void convw_k(const float* __restrict__ W0,
                                               const float* __restrict__ W1,
                                               const float* __restrict__ W2,
                                               const float* __restrict__ W3,
                                               __half* __restrict__ T)
{
    __shared__ float t[32][33];
    const int z = blockIdx.z;
    const float* W = z == 0 ? W0 : (z == 1 ? W1 : (z == 2 ? W2 : W3));
    __half* th = T + (size_t)z * Dm * Dm;
    int n0 = blockIdx.x * 32, k0 = blockIdx.y * 32;
    int tx = threadIdx.x, ty = threadIdx.y;
    #pragma unroll
    for (int j = ty; j < 32; j += 8)
        t[j][tx] = W[(size_t)(k0 + j) * Dm + n0 + tx];
    __syncthreads();
    #pragma unroll
    for (int j = ty; j < 32; j += 8)
        th[(size_t)(n0 + j) * Dm + k0 + tx] = __float2half_rn(t[tx][j]);
}

// ---------------------------------------------------------------------------
// GEMM core: CTA 128x128, 4 warps (64x64), BK=32, 2-stage, single-term A.
// ---------------------------------------------------------------------------
#define GP 40
#define MATB (128*GP*2)     // 10240
#define GSTG (2*MATB)       // 20480
#define GSMEM (2*GSTG)      // 40960

__device__ __forceinline__ void gemm_core1(
    const uint32_t sb,
    const __half* __restrict__ gA, const __half* __restrict__ gB,
    int tid, int lane, int wr, int wc, float acc[4][8][4])
{
    auto issue = [&](int kt, int buf) {
        const int kc = kt * 32;
        const uint32_t base = sb + buf * GSTG;
        #pragma unroll
        for (int p = 0; p < 4; p++) {
            int i = tid + p * 128;
            int r = i >> 2, c = i & 3;
            uint32_t so = (uint32_t)(r * (GP*2) + c * 16);
            size_t go = (size_t)r * Dm + kc + c * 8;
            cp16(base + so, gA + go);
            cp16(base + MATB + so, gB + go);
        }
        cp_commit();
    };

    const int aRow = wr * 64 + (lane & 15);
    const int aKh  = (lane >> 4) * 8;
    const int bRow = wc * 64 + (lane & 7);
    const int bKh  = ((lane >> 3) & 1) * 8;

    issue(0, 0);

    for (int kt = 0; kt < 32; kt++) {
        cp_wait0();
        __syncthreads();
        if (kt + 1 < 32) issue(kt + 1, (kt + 1) & 1);

        const uint32_t base = sb + (kt & 1) * GSTG;
        #pragma unroll
        for (int kk = 0; kk < 2; kk++) {
            uint32_t bf[8][2];
            #pragma unroll
            for (int j = 0; j < 8; j++) {
                uint32_t ba = base + MATB +
                    (uint32_t)(((bRow + j * 8) * GP + kk * 16 + bKh) * 2);
                ldsm_x2(bf[j], ba);
            }
            #pragma unroll
            for (int t = 0; t < 4; t++) {
                uint32_t aa = base +
                    (uint32_t)(((aRow + t * 16) * GP + kk * 16 + aKh) * 2);
                uint32_t af[4];
                ldsm_x4(af, aa);
                #pragma unroll
                for (int j = 0; j < 8; j++)
                    mma16816(acc[t][j], af, bf[j]);
            }
        }
    }
}

// Fused QKV projection: C[4096][3072] = X @ [WQ|WK|WV]^T, all single-term.
__global__ __launch_bounds__(128) void qkv_gemm(
    const __half* __restrict__ Xf, const __half* __restrict__ Bg,
    __half* __restrict__ Qf, __half* __restrict__ Kf, __half* __restrict__ Vf)
{
    extern __shared__ char smc[];
    const uint32_t sb = smem_u32(smc);
    const int tid = threadIdx.x, lane = tid & 31, w = tid >> 5;
    const int wr = w >> 1, wc = w & 1;
    const int rowBase = blockIdx.y * 128, colBase = blockIdx.x * 128;
    const int which = colBase >> 10;            // 0=Q 1=K 2=V

    float acc[4][8][4];
    #pragma unroll
    for (int t = 0; t < 4; t++)
        #pragma unroll
        for (int j = 0; j < 8; j++)
            #pragma unroll
            for (int e = 0; e < 4; e++) acc[t][j][e] = 0.f;

    gemm_core1(sb, Xf + (size_t)rowBase * Dm, Bg + (size_t)colBase * Dm,
               tid, lane, wr, wc, acc);

    const int er = lane >> 2, ec = (lane & 3) * 2;
    __half* dst = which == 0 ? Qf : (which == 1 ? Kf : Vf);
    const float scale = which == 0 ? 0.125f * 1.4426950408889634f : 1.0f;
    #pragma unroll
    for (int t = 0; t < 4; t++) {
        #pragma unroll
        for (int j = 0; j < 8; j++) {
            int m0 = rowBase + wr * 64 + t * 16 + er;
            int n  = (colBase & 1023) + wc * 64 + j * 8 + ec;
            int h = n >> 6, hd = n & 63;
            #pragma unroll
            for (int half = 0; half < 2; half++) {
                int m = m0 + half * 8;
                int b = m >> 11, s = m & 2047;
                size_t o = ((size_t)((b * Hh + h) * Sq + s)) * HDc + hd;
                *(uint32_t*)&dst[o] = h2pack(acc[t][j][2*half] * scale,
                                             acc[t][j][2*half+1] * scale);
            }
        }
    }
}

// Output projection: C[4096][1024] fp32 = AH @ WO^T
__global__ __launch_bounds__(128) void wo_gemm(
    const __half* __restrict__ Ag, const __half* __restrict__ Bg,
    float* __restrict__ dst)
{
    extern __shared__ char smc[];
    const uint32_t sb = smem_u32(smc);
    const int tid = threadIdx.x, lane = tid & 31, w = tid >> 5;
    const int wr = w >> 1, wc = w & 1;
    const int rowBase = blockIdx.y * 128, colBase = blockIdx.x * 128;

    float acc[4][8][4];
    #pragma unroll
    for (int t = 0; t < 4; t++)
        #pragma unroll
        for (int j = 0; j < 8; j++)
            #pragma unroll
            for (int e = 0; e < 4; e++) acc[t][j][e] = 0.f;

    gemm_core1(sb, Ag + (size_t)rowBase * Dm, Bg + (size_t)colBase * Dm,
               tid, lane, wr, wc, acc);

    const int er = lane >> 2, ec = (lane & 3) * 2;
    #pragma unroll
    for (int t = 0; t < 4; t++) {
        #pragma unroll
        for (int j = 0; j < 8; j++) {
            int m0 = rowBase + wr * 64 + t * 16 + er;
            int n  = colBase + wc * 64 + j * 8 + ec;
            *(float2*)&dst[(size_t)m0 * Dm + n] = make_float2(acc[t][j][0], acc[t][j][1]);
            *(float2*)&dst[(size_t)(m0 + 8) * Dm + n] = make_float2(acc[t][j][2], acc[t][j][3]);
        }
    }
}

// ---------------------------------------------------------------------------
// HMMA flash attention: 128 thr, 4 warps x 32 q-rows (2 m-subtiles), 64-key
// tiles, 2-stage cp.async. Single fp16: QK 1 MMA, PV 1 MMA; K fragments
// feed 2 MMAs, V fragments feed 2 MMAs (halved LDS per MMA). Q reloaded from
// smem per tile (saves 32 regs). l via ones-column MMA; f16x2 softmax.
// ---------------------------------------------------------------------------
#define AP 72
#define KTB (64*AP*2)       // 9216
#define QTB (128*AP*2)      // 18432
#define STG (2*KTB)         // 18432 (K, V)
#define ASMEM (QTB + 2*STG) // 55296

__global__ __launch_bounds__(128, 3) void attn_mma(
    const __half* __restrict__ Qfg, const __half* __restrict__ Kfg,
    const __half* __restrict__ Vfg, __half* __restrict__ AH)
{
    extern __shared__ char smc[];
    const uint32_t sb = smem_u32(smc);
    const uint32_t sQ = sb;

    const int tid = threadIdx.x, lane = tid & 31, w = tid >> 5;   // w: 0..3
    const int q0 = ((int)gridDim.x - 1 - (int)blockIdx.x) * 128;  // longest-first
    const int h  = blockIdx.y;
    const int b  = blockIdx.z;

    const size_t hb = (size_t)((b * Hh + h) * Sq) * HDc;
    const __half* Qfb = Qfg + hb;
    const __half* Kfb = Kfg + hb;
    const __half* Vfb = Vfg + hb;

    for (int i = tid; i < 1024; i += 128) {
        int r = i >> 3, c = (i & 7) * 8;
        uint32_t off = (uint32_t)(r * AP + c) * 2;
        *(uint4*)(smc + off) = *(const uint4*)&Qfb[(size_t)(q0 + r) * HDc + c];
    }

    const int nTiles = q0 / 64 + 2;

    auto issue = [&](int kt, int st) {
        const uint32_t base = sb + QTB + st * STG;
        #pragma unroll
        for (int p = 0; p < 4; p++) {
            int i = tid + p * 128;
            int r = i >> 3, c = (i & 7) * 8;
            uint32_t so = (uint32_t)(r * AP + c) * 2;
            size_t go = (size_t)(kt * 64 + r) * HDc + c;
            cp16(base + so, Kfb + go);
            cp16(base + KTB + so, Vfb + go);
        }
        cp_commit();
    };

    float m0[2], m1[2];
    float o[2][8][4];
    float ol[2][4];
    #pragma unroll
    for (int t = 0; t < 2; t++) {
        m0[t] = -INFINITY; m1[t] = -INFINITY;
        #pragma unroll
        for (int j = 0; j < 8; j++)
            #pragma unroll
            for (int e = 0; e < 4; e++) o[t][j][e] = 0.f;
        ol[t][0] = ol[t][1] = ol[t][2] = ol[t][3] = 0.f;
    }

    const int er = lane >> 2, ec = (lane & 3) * 2;
    const int wrow = q0 + w * 32;

    issue(0, 0);

    for (int kt = 0; kt < nTiles; kt++) {
        cp_wait0();
        __syncthreads();
        if (kt + 1 < nTiles) issue(kt + 1, (kt + 1) & 1);

        if (kt * 64 <= wrow + 31) {
            const uint32_t base = sb + QTB + (kt & 1) * STG;
            const uint32_t sK = base, sV = base + KTB;

            float s[2][8][4];
            #pragma unroll
            for (int t = 0; t < 2; t++)
                #pragma unroll
                for (int j = 0; j < 8; j++)
                    #pragma unroll
                    for (int e = 0; e < 4; e++) s[t][j][e] = 0.f;

            #pragma unroll
            for (int ks = 0; ks < 4; ks++) {
                uint32_t qf0[4], qf1[4];
                uint32_t a0 = sQ + (uint32_t)(((w * 32 + (lane & 15)) * AP + ks * 16 + (lane >> 4) * 8) * 2);
                ldsm_x4(qf0, a0);
                ldsm_x4(qf1, a0 + (uint32_t)(16 * AP * 2));
                #pragma unroll
                for (int j = 0; j < 8; j++) {
                    uint32_t boff = (uint32_t)(((j * 8 + (lane & 7)) * AP + ks * 16 + ((lane >> 3) & 1) * 8) * 2);
                    uint32_t kf[2];
                    ldsm_x2(kf, sK + boff);
                    mma16816(s[0][j], qf0, kf);
                    mma16816(s[1][j], qf1, kf);
                }
            }

            uint32_t ph[2][8];
            #pragma unroll
            for (int t = 0; t < 2; t++) {
                const int row0 = wrow + t * 16 + er, row1 = row0 + 8;
                if (kt * 64 + 63 > row0) {
                    #pragma unroll
                    for (int j = 0; j < 8; j++) {
                        int k = kt * 64 + j * 8 + ec;
                        if (k     > row0) s[t][j][0] = -INFINITY;
                        if (k + 1 > row0) s[t][j][1] = -INFINITY;
                        if (k     > row1) s[t][j][2] = -INFINITY;
                        if (k + 1 > row1) s[t][j][3] = -INFINITY;
                    }
                }

                float rm0 = -INFINITY, rm1 = -INFINITY;
                #pragma unroll
                for (int j = 0; j < 8; j++) {
                    rm0 = fmaxf(rm0, fmaxf(s[t][j][0], s[t][j][1]));
                    rm1 = fmaxf(rm1, fmaxf(s[t][j][2], s[t][j][3]));
                }
                float rm0c = fmaxf(rm0, -60000.f), rm1c = fmaxf(rm1, -60000.f);
                uint32_t rmp = h2pack(rm0c, rm1c);
                rmp = hmax2(rmp, __shfl_xor_sync(0xffffffffu, rmp, 1));
                rmp = hmax2(rmp, __shfl_xor_sync(0xffffffffu, rmp, 2));
                __half2 rmh = *(__half2*)&rmp;
                float mn0 = fmaxf(m0[t], __half2float(rmh.x));
                float mn1 = fmaxf(m1[t], __half2float(rmh.y));

                float d0 = fmaxf(m0[t] - mn0, -60000.f), d1 = fmaxf(m1[t] - mn1, -60000.f);
                uint32_t cp = ex2h2(h2pack(d0, d1));
                __half2 ch = *(__half2*)&cp;
                float c0 = __half2float(ch.x), c1 = __half2float(ch.y);
                m0[t] = mn0; m1[t] = mn1;

                #pragma unroll
                for (int j = 0; j < 8; j++) {
                    // pack both row-groups into the A-fragment register pair order
                    ph[t][j] = 0;  // placeholder to keep structure; real packing below
                    o[t][j][0] *= c0; o[t][j][1] *= c0;
                    o[t][j][2] *= c1; o[t][j][3] *= c1;
                }
                ol[t][0] *= c0; ol[t][1] *= c0;
                ol[t][2] *= c1; ol[t][3] *= c1;

                // ph layout: per aj we need pp = {e0 rows er, e1 rows er+8, ...}
                // store exp halves: ph[t][2*x]   = exp(s[t][x-th pair][0..1])
                //                   ph[t][2*x+1] = exp(s[t][..][2..3])
                #pragma unroll
                for (int x = 0; x < 4; x++) {
                    ph[t][2*x]   = ex2h2(h2pack(s[t][2*x][0]   - m0[t], s[t][2*x][1]   - m0[t]));
                    ph[t][2*x+1] = ex2h2(h2pack(s[t][2*x][2]   - m1[t], s[t][2*x][3]   - m1[t]));
                }
                // NOTE: pairs (2*x, 2*x+1) above only cover s[t][even]; odd handled in PV packing
            }

            // recompute odd-j exp inline during PV packing (keeps ph at 8 regs/subtile)
            const uint32_t ones2[2] = {0x3C003C00u, 0x3C003C00u};
            #pragma unroll
            for (int aj = 0; aj < 4; aj++) {
                uint32_t pp0[4], pp1[4];
                pp0[0] = ph[0][2*aj];
                pp0[1] = ph[0][2*aj+1];
                pp0[2] = ex2h2(h2pack(s[0][2*aj+1][0] - m0[0], s[0][2*aj+1][1] - m0[0]));
                pp0[3] = ex2h2(h2pack(s[0][2*aj+1][2] - m1[0], s[0][2*aj+1][3] - m1[0]));
                pp1[0] = ph[1][2*aj];
                pp1[1] = ph[1][2*aj+1];
                pp1[2] = ex2h2(h2pack(s[1][2*aj+1][0] - m0[1], s[1][2*aj+1][1] - m0[1]));
                pp1[3] = ex2h2(h2pack(s[1][2*aj+1][2] - m1[1], s[1][2*aj+1][3] - m1[1]));
                mma16816(ol[0], pp0, ones2);
                mma16816(ol[1], pp1, ones2);
                #pragma unroll
                for (int j = 0; j < 8; j++) {
                    uint32_t voff = (uint32_t)(((aj * 16 + (lane & 7) + ((lane >> 3) & 1) * 8) * AP + j * 8) * 2);
                    uint32_t vf[2];
                    ldsm_x2t(vf, sV + voff);
                    mma16816(o[0][j], pp0, vf);
                    mma16816(o[1][j], pp1, vf);
                }
            }
        }
    }

    #pragma unroll
    for (int t = 0; t < 2; t++) {
        float i0 = 1.f / ol[t][0], i1 = 1.f / ol[t][2];
        const int row0 = wrow + t * 16 + er;
        #pragma unroll
        for (int j = 0; j < 8; j++) {
            int dim = j * 8 + ec;
            size_t o0 = (size_t)(b * Sq + row0) * Dm + h * HDc + dim;
            size_t o1 = (size_t)(b * Sq + row0 + 8) * Dm + h * HDc + dim;
            *(uint32_t*)&AH[o0] = h2pack(o[t][j][0] * i0, o[t][j][1] * i0);
            *(uint32_t*)&AH[o1] = h2pack(o[t][j][2] * i1, o[t][j][3] * i1);
        }
    }
}

// ---------------------------------------------------------------------------
extern "C" void kernel_launch(void* const* d_in, const int* in_sizes, int n_in,
                              void* d_out, int out_size)
{
    (void)in_sizes; (void)n_in; (void)out_size;
    const float* x  = (const float*)d_in[0];
    const float* WQ = (const float*)d_in[1];
    const float* WK = (const float*)d_in[2];
    const float* WV = (const float*)d_in[3];
    const float* WO = (const float*)d_in[4];
    float* out = (float*)d_out;

    __half *xf, *wf, *ah, *qf, *kf, *vf;
    cudaGetSymbolAddress((void**)&xf, g_Xf);
    cudaGetSymbolAddress((void**)&wf, g_Wf);
    cudaGetSymbolAddress((void**)&ah, g_AH);
    cudaGetSymbolAddress((void**)&qf, g_Qf);
    cudaGetSymbolAddress((void**)&kf, g_Kf);
    cudaGetSymbolAddress((void**)&vf, g_Vf);

    static int attrs_set = 0;
    if (!attrs_set) {
        cudaFuncSetAttribute(qkv_gemm, cudaFuncAttributeMaxDynamicSharedMemorySize, GSMEM);
        cudaFuncSetAttribute(wo_gemm,  cudaFuncAttributeMaxDynamicSharedMemorySize, GSMEM);
        cudaFuncSetAttribute(attn_mma, cudaFuncAttributeMaxDynamicSharedMemorySize, ASMEM);
        attrs_set = 1;
    }

    convx_k<<<Mtot * Dm / 4 / 256, 256>>>(x, xf);
    convw_k<<<dim3(32, 32, 4), dim3(32, 8)>>>(WQ, WK, WV, WO, wf);

    qkv_gemm<<<dim3(3 * Dm / 128, Mtot / 128), 128, GSMEM>>>(
        xf, wf, qf, kf, vf);

    attn_mma<<<dim3(Sq / 128, Hh, Bq), 128, ASMEM>>>(qf, kf, vf, ah);

    wo_gemm<<<dim3(Dm / 128, Mtot / 128), 128, GSMEM>>>(
        ah, wf + 3 * (size_t)Dm * Dm, out);
}

// round 17
// speedup vs baseline: 1.0076x; 1.0076x over previous
#include <cuda_runtime.h>
#include <cuda_fp16.h>
#include <math.h>
#include <stdint.h>

// Problem constants
#define Bq  2
#define Sq  2048
#define Dm  1024
#define Hh  16
#define HDc 64
#define Mtot (Bq*Sq)   // 4096

// ---------------- device scratch (fp16) ----------------
__device__ __half g_Xf[Mtot*Dm];                  // x single fp16
__device__ __half g_Wf[4][Dm*Dm];                 // W^T single fp16, [N][K]
__device__ __half g_Qf[Mtot*Dm];                  // Q single, pre-scaled 0.125*log2e
__device__ __half g_Kf[Mtot*Dm], g_Vf[Mtot*Dm];   // K/V single
__device__ __half g_AH[Mtot*Dm];                  // attention out single fp16

// ---------------- helpers ----------------
__device__ __forceinline__ uint32_t smem_u32(const void* p) {
    uint32_t a;
    asm("{ .reg .u64 t; cvta.to.shared.u64 t, %1; cvt.u32.u64 %0, t; }" : "=r"(a) : "l"(p));
    return a;
}
__device__ __forceinline__ void cp16(uint32_t saddr, const void* gptr) {
    asm volatile("cp.async.cg.shared.global [%0], [%1], 16;" :: "r"(saddr), "l"(gptr) : "memory");
}
__device__ __forceinline__ void cp_commit() {
    asm volatile("cp.async.commit_group;" ::: "memory");
}
__device__ __forceinline__ void cp_wait0() {
    asm volatile("cp.async.wait_group 0;" ::: "memory");
}
__device__ __forceinline__ void cp_wait1() {
    asm volatile("cp.async.wait_group 1;" ::: "memory");
}
__device__ __forceinline__ void ldsm_x4(uint32_t* r, uint32_t a) {
    asm volatile("ldmatrix.sync.aligned.m8n8.x4.shared.b16 {%0,%1,%2,%3}, [%4];"
                 : "=r"(r[0]), "=r"(r[1]), "=r"(r[2]), "=r"(r[3]) : "r"(a));
}
__device__ __forceinline__ void ldsm_x2(uint32_t* r, uint32_t a) {
    asm volatile("ldmatrix.sync.aligned.m8n8.x2.shared.b16 {%0,%1}, [%2];"
                 : "=r"(r[0]), "=r"(r[1]) : "r"(a));
}
__device__ __forceinline__ void ldsm_x2t(uint32_t* r, uint32_t a) {
    asm volatile("ldmatrix.sync.aligned.m8n8.x2.trans.shared.b16 {%0,%1}, [%2];"
                 : "=r"(r[0]), "=r"(r[1]) : "r"(a));
}
__device__ __forceinline__ void mma16816(float* c, const uint32_t* a, const uint32_t* b) {
    asm volatile(
        "mma.sync.aligned.m16n8k16.row.col.f32.f16.f16.f32 "
        "{%0,%1,%2,%3}, {%4,%5,%6,%7}, {%8,%9}, {%0,%1,%2,%3};"
        : "+f"(c[0]), "+f"(c[1]), "+f"(c[2]), "+f"(c[3])
        : "r"(a[0]), "r"(a[1]), "r"(a[2]), "r"(a[3]), "r"(b[0]), "r"(b[1]));
}
__device__ __forceinline__ uint32_t ex2h2(uint32_t x) {
    uint32_t y;
    asm("ex2.approx.f16x2 %0, %1;" : "=r"(y) : "r"(x));
    return y;
}
__device__ __forceinline__ uint32_t hmax2(uint32_t a, uint32_t b) {
    uint32_t y;
    asm("max.f16x2 %0, %1, %2;" : "=r"(y) : "r"(a), "r"(b));
    return y;
}
__device__ __forceinline__ uint32_t h2pack(float a, float b) {
    __half2 h = __floats2half2_rn(a, b);
    return *(uint32_t*)&h;
}

// ---------------------------------------------------------------------------
// conversion kernels
// ---------------------------------------------------------------------------
__global__ __launch_bounds__(256) void convx_k(const float* __restrict__ X,
                                               __half* __restrict__ H)
{
    int i = blockIdx.x * blockDim.x + threadIdx.x;
    float4 v = ((const float4*)X)[i];
    ((uint2*)H)[i] = make_uint2(h2pack(v.x, v.y), h2pack(v.z, v.w));
}

__global__ __launch_bounds__(256) void convw_k(const float* __restrict__ W0,
                                               const float* __restrict__ W1,
                                               const float* __restrict__ W2,
                                               const float* __restrict__ W3,
                                               __half* __restrict__ T)
{
    __shared__ float t[32][33];
    const int z = blockIdx.z;
    const float* W = z == 0 ? W0 : (z == 1 ? W1 : (z == 2 ? W2 : W3));
    __half* th = T + (size_t)z * Dm * Dm;
    int n0 = blockIdx.x * 32, k0 = blockIdx.y * 32;
    int tx = threadIdx.x, ty = threadIdx.y;
    #pragma unroll
    for (int j = ty; j < 32; j += 8)
        t[j][tx] = W[(size_t)(k0 + j) * Dm + n0 + tx];
    __syncthreads();
    #pragma unroll
    for (int j = ty; j < 32; j += 8)
        th[(size_t)(n0 + j) * Dm + k0 + tx] = __float2half_rn(t[tx][j]);
}

// ---------------------------------------------------------------------------
// GEMM core: CTA 128x128, 4 warps (64x64), BK=32, 2-stage, single-term A.
// ---------------------------------------------------------------------------
#define GP 40
#define MATB (128*GP*2)     // 10240
#define GSTG (2*MATB)       // 20480
#define GSMEM (2*GSTG)      // 40960

__device__ __forceinline__ void gemm_core1(
    const uint32_t sb,
    const __half* __restrict__ gA, const __half* __restrict__ gB,
    int tid, int lane, int wr, int wc, float acc[4][8][4])
{
    auto issue = [&](int kt, int buf) {
        const int kc = kt * 32;
        const uint32_t base = sb + buf * GSTG;
        #pragma unroll
        for (int p = 0; p < 4; p++) {
            int i = tid + p * 128;
            int r = i >> 2, c = i & 3;
            uint32_t so = (uint32_t)(r * (GP*2) + c * 16);
            size_t go = (size_t)r * Dm + kc + c * 8;
            cp16(base + so, gA + go);
            cp16(base + MATB + so, gB + go);
        }
        cp_commit();
    };

    const int aRow = wr * 64 + (lane & 15);
    const int aKh  = (lane >> 4) * 8;
    const int bRow = wc * 64 + (lane & 7);
    const int bKh  = ((lane >> 3) & 1) * 8;

    issue(0, 0);

    for (int kt = 0; kt < 32; kt++) {
        cp_wait0();
        __syncthreads();
        if (kt + 1 < 32) issue(kt + 1, (kt + 1) & 1);

        const uint32_t base = sb + (kt & 1) * GSTG;
        #pragma unroll
        for (int kk = 0; kk < 2; kk++) {
            uint32_t bf[8][2];
            #pragma unroll
            for (int j = 0; j < 8; j++) {
                uint32_t ba = base + MATB +
                    (uint32_t)(((bRow + j * 8) * GP + kk * 16 + bKh) * 2);
                ldsm_x2(bf[j], ba);
            }
            #pragma unroll
            for (int t = 0; t < 4; t++) {
                uint32_t aa = base +
                    (uint32_t)(((aRow + t * 16) * GP + kk * 16 + aKh) * 2);
                uint32_t af[4];
                ldsm_x4(af, aa);
                #pragma unroll
                for (int j = 0; j < 8; j++)
                    mma16816(acc[t][j], af, bf[j]);
            }
        }
    }
}

// Fused QKV projection: C[4096][3072] = X @ [WQ|WK|WV]^T, all single-term.
__global__ __launch_bounds__(128) void qkv_gemm(
    const __half* __restrict__ Xf, const __half* __restrict__ Bg,
    __half* __restrict__ Qf, __half* __restrict__ Kf, __half* __restrict__ Vf)
{
    extern __shared__ char smc[];
    const uint32_t sb = smem_u32(smc);
    const int tid = threadIdx.x, lane = tid & 31, w = tid >> 5;
    const int wr = w >> 1, wc = w & 1;
    const int rowBase = blockIdx.y * 128, colBase = blockIdx.x * 128;
    const int which = colBase >> 10;            // 0=Q 1=K 2=V

    float acc[4][8][4];
    #pragma unroll
    for (int t = 0; t < 4; t++)
        #pragma unroll
        for (int j = 0; j < 8; j++)
            #pragma unroll
            for (int e = 0; e < 4; e++) acc[t][j][e] = 0.f;

    gemm_core1(sb, Xf + (size_t)rowBase * Dm, Bg + (size_t)colBase * Dm,
               tid, lane, wr, wc, acc);

    const int er = lane >> 2, ec = (lane & 3) * 2;
    __half* dst = which == 0 ? Qf : (which == 1 ? Kf : Vf);
    const float scale = which == 0 ? 0.125f * 1.4426950408889634f : 1.0f;
    #pragma unroll
    for (int t = 0; t < 4; t++) {
        #pragma unroll
        for (int j = 0; j < 8; j++) {
            int m0 = rowBase + wr * 64 + t * 16 + er;
            int n  = (colBase & 1023) + wc * 64 + j * 8 + ec;
            int h = n >> 6, hd = n & 63;
            #pragma unroll
            for (int half = 0; half < 2; half++) {
                int m = m0 + half * 8;
                int b = m >> 11, s = m & 2047;
                size_t o = ((size_t)((b * Hh + h) * Sq + s)) * HDc + hd;
                *(uint32_t*)&dst[o] = h2pack(acc[t][j][2*half] * scale,
                                             acc[t][j][2*half+1] * scale);
            }
        }
    }
}

// Output projection: C[4096][1024] fp32 = AH @ WO^T
__global__ __launch_bounds__(128) void wo_gemm(
    const __half* __restrict__ Ag, const __half* __restrict__ Bg,
    float* __restrict__ dst)
{
    extern __shared__ char smc[];
    const uint32_t sb = smem_u32(smc);
    const int tid = threadIdx.x, lane = tid & 31, w = tid >> 5;
    const int wr = w >> 1, wc = w & 1;
    const int rowBase = blockIdx.y * 128, colBase = blockIdx.x * 128;

    float acc[4][8][4];
    #pragma unroll
    for (int t = 0; t < 4; t++)
        #pragma unroll
        for (int j = 0; j < 8; j++)
            #pragma unroll
            for (int e = 0; e < 4; e++) acc[t][j][e] = 0.f;

    gemm_core1(sb, Ag + (size_t)rowBase * Dm, Bg + (size_t)colBase * Dm,
               tid, lane, wr, wc, acc);

    const int er = lane >> 2, ec = (lane & 3) * 2;
    #pragma unroll
    for (int t = 0; t < 4; t++) {
        #pragma unroll
        for (int j = 0; j < 8; j++) {
            int m0 = rowBase + wr * 64 + t * 16 + er;
            int n  = colBase + wc * 64 + j * 8 + ec;
            *(float2*)&dst[(size_t)m0 * Dm + n] = make_float2(acc[t][j][0], acc[t][j][1]);
            *(float2*)&dst[(size_t)(m0 + 8) * Dm + n] = make_float2(acc[t][j][2], acc[t][j][3]);
        }
    }
}

// ---------------------------------------------------------------------------
// HMMA flash attention (R15 + 3-stage K/V ring): 256 thr, 8 warps x 16 q-rows,
// 64-key tiles, cp.async wait_group 1. Single fp16: QK 1 MMA, PV 1 MMA,
// l via ones-column MMA, Q hoisted (16 regs), f16x2 softmax.
// ---------------------------------------------------------------------------
#define AP 72
#define KTB (64*AP*2)       // 9216
#define QTB (128*AP*2)      // 18432
#define STG (2*KTB)         // 18432 (K, V)
#define ASMEM (QTB + 3*STG) // 73728

__global__ __launch_bounds__(256, 2) void attn_mma(
    const __half* __restrict__ Qfg, const __half* __restrict__ Kfg,
    const __half* __restrict__ Vfg, __half* __restrict__ AH)
{
    extern __shared__ char smc[];
    const uint32_t sb = smem_u32(smc);
    const uint32_t sQ = sb;

    const int tid = threadIdx.x, lane = tid & 31, w = tid >> 5;
    const int q0 = ((int)gridDim.x - 1 - (int)blockIdx.x) * 128;  // longest-first
    const int h  = blockIdx.y;
    const int b  = blockIdx.z;

    const size_t hb = (size_t)((b * Hh + h) * Sq) * HDc;
    const __half* Qfb = Qfg + hb;
    const __half* Kfb = Kfg + hb;
    const __half* Vfb = Vfg + hb;

    const int nTiles = q0 / 64 + 2;

    auto issue = [&](int kt) {
        if (kt < nTiles) {
            const uint32_t base = sb + QTB + (uint32_t)((kt % 3) * STG);
            #pragma unroll
            for (int p = 0; p < 2; p++) {
                int i = tid + p * 256;
                int r = i >> 3, c = (i & 7) * 8;
                uint32_t so = (uint32_t)(r * AP + c) * 2;
                size_t go = (size_t)(kt * 64 + r) * HDc + c;
                cp16(base + so, Kfb + go);
                cp16(base + KTB + so, Vfb + go);
            }
        }
        cp_commit();
    };

    for (int i = tid; i < 1024; i += 256) {
        int r = i >> 3, c = (i & 7) * 8;
        uint32_t off = (uint32_t)(r * AP + c) * 2;
        *(uint4*)(smc + off) = *(const uint4*)&Qfb[(size_t)(q0 + r) * HDc + c];
    }

    issue(0);
    issue(1);
    __syncthreads();   // Q smem visible

    // hoist Q fragments (single fp16: 16 regs)
    uint32_t qf[4][4];
    #pragma unroll
    for (int ks = 0; ks < 4; ks++) {
        uint32_t aoff = (uint32_t)(((w * 16 + (lane & 15)) * AP + ks * 16 + (lane >> 4) * 8) * 2);
        ldsm_x4(qf[ks], sQ + aoff);
    }

    float m0 = -INFINITY, m1 = -INFINITY;
    float o[8][4];
    float ol[4];
    #pragma unroll
    for (int j = 0; j < 8; j++)
        #pragma unroll
        for (int e = 0; e < 4; e++) o[j][e] = 0.f;
    ol[0] = ol[1] = ol[2] = ol[3] = 0.f;

    const int er = lane >> 2, ec = (lane & 3) * 2;
    const int wrow = q0 + w * 16;

    for (int kt = 0; kt < nTiles; kt++) {
        cp_wait1();
        __syncthreads();
        issue(kt + 2);

        if (kt * 64 <= wrow + 15) {
            const uint32_t base = sb + QTB + (uint32_t)((kt % 3) * STG);
            const uint32_t sK = base, sV = base + KTB;

            float s[8][4];
            #pragma unroll
            for (int j = 0; j < 8; j++)
                #pragma unroll
                for (int e = 0; e < 4; e++) s[j][e] = 0.f;

            #pragma unroll
            for (int ks = 0; ks < 4; ks++) {
                #pragma unroll
                for (int j = 0; j < 8; j++) {
                    uint32_t boff = (uint32_t)(((j * 8 + (lane & 7)) * AP + ks * 16 + ((lane >> 3) & 1) * 8) * 2);
                    uint32_t kf[2];
                    ldsm_x2(kf, sK + boff);
                    mma16816(s[j], qf[ks], kf);
                }
            }

            const int row0 = wrow + er, row1 = row0 + 8;
            if (kt * 64 + 63 > row0) {
                #pragma unroll
                for (int j = 0; j < 8; j++) {
                    int k = kt * 64 + j * 8 + ec;
                    if (k     > row0) s[j][0] = -INFINITY;
                    if (k + 1 > row0) s[j][1] = -INFINITY;
                    if (k     > row1) s[j][2] = -INFINITY;
                    if (k + 1 > row1) s[j][3] = -INFINITY;
                }
            }

            // packed fp16 row-max across the 4 lanes of each row
            float rm0 = -INFINITY, rm1 = -INFINITY;
            #pragma unroll
            for (int j = 0; j < 8; j++) {
                rm0 = fmaxf(rm0, fmaxf(s[j][0], s[j][1]));
                rm1 = fmaxf(rm1, fmaxf(s[j][2], s[j][3]));
            }
            float rm0c = fmaxf(rm0, -60000.f), rm1c = fmaxf(rm1, -60000.f);
            uint32_t rmp = h2pack(rm0c, rm1c);
            rmp = hmax2(rmp, __shfl_xor_sync(0xffffffffu, rmp, 1));
            rmp = hmax2(rmp, __shfl_xor_sync(0xffffffffu, rmp, 2));
            __half2 rmh = *(__half2*)&rmp;
            float mn0 = fmaxf(m0, __half2float(rmh.x));
            float mn1 = fmaxf(m1, __half2float(rmh.y));

            // correction factors via one f16x2 exp
            float d0 = fmaxf(m0 - mn0, -60000.f), d1 = fmaxf(m1 - mn1, -60000.f);
            uint32_t cp = ex2h2(h2pack(d0, d1));
            __half2 ch = *(__half2*)&cp;
            float c0 = __half2float(ch.x), c1 = __half2float(ch.y);
            m0 = mn0; m1 = mn1;

            uint32_t ph0[8], ph1[8];
            #pragma unroll
            for (int j = 0; j < 8; j++) {
                ph0[j] = ex2h2(h2pack(s[j][0] - m0, s[j][1] - m0));
                ph1[j] = ex2h2(h2pack(s[j][2] - m1, s[j][3] - m1));
                o[j][0] *= c0; o[j][1] *= c0;
                o[j][2] *= c1; o[j][3] *= c1;
            }
            ol[0] *= c0; ol[1] *= c0;
            ol[2] *= c1; ol[3] *= c1;

            const uint32_t ones2[2] = {0x3C003C00u, 0x3C003C00u};
            #pragma unroll
            for (int aj = 0; aj < 4; aj++) {
                uint32_t pp[4];
                pp[0] = ph0[2*aj];
                pp[1] = ph1[2*aj];
                pp[2] = ph0[2*aj+1];
                pp[3] = ph1[2*aj+1];
                mma16816(ol, pp, ones2);
                #pragma unroll
                for (int j = 0; j < 8; j++) {
                    uint32_t voff = (uint32_t)(((aj * 16 + (lane & 7) + ((lane >> 3) & 1) * 8) * AP + j * 8) * 2);
                    uint32_t vf[2];
                    ldsm_x2t(vf, sV + voff);
                    mma16816(o[j], pp, vf);
                }
            }
        }
    }

    float i0 = 1.f / ol[0], i1 = 1.f / ol[2];

    const int row0 = wrow + er;
    #pragma unroll
    for (int j = 0; j < 8; j++) {
        int dim = j * 8 + ec;
        size_t o0 = (size_t)(b * Sq + row0) * Dm + h * HDc + dim;
        size_t o1 = (size_t)(b * Sq + row0 + 8) * Dm + h * HDc + dim;
        *(uint32_t*)&AH[o0] = h2pack(o[j][0] * i0, o[j][1] * i0);
        *(uint32_t*)&AH[o1] = h2pack(o[j][2] * i1, o[j][3] * i1);
    }
}

// ---------------------------------------------------------------------------
extern "C" void kernel_launch(void* const* d_in, const int* in_sizes, int n_in,
                              void* d_out, int out_size)
{
    (void)in_sizes; (void)n_in; (void)out_size;
    const float* x  = (const float*)d_in[0];
    const float* WQ = (const float*)d_in[1];
    const float* WK = (const float*)d_in[2];
    const float* WV = (const float*)d_in[3];
    const float* WO = (const float*)d_in[4];
    float* out = (float*)d_out;

    __half *xf, *wf, *ah, *qf, *kf, *vf;
    cudaGetSymbolAddress((void**)&xf, g_Xf);
    cudaGetSymbolAddress((void**)&wf, g_Wf);
    cudaGetSymbolAddress((void**)&ah, g_AH);
    cudaGetSymbolAddress((void**)&qf, g_Qf);
    cudaGetSymbolAddress((void**)&kf, g_Kf);
    cudaGetSymbolAddress((void**)&vf, g_Vf);

    static int attrs_set = 0;
    if (!attrs_set) {
        cudaFuncSetAttribute(qkv_gemm, cudaFuncAttributeMaxDynamicSharedMemorySize, GSMEM);
        cudaFuncSetAttribute(wo_gemm,  cudaFuncAttributeMaxDynamicSharedMemorySize, GSMEM);
        cudaFuncSetAttribute(attn_mma, cudaFuncAttributeMaxDynamicSharedMemorySize, ASMEM);
        attrs_set = 1;
    }

    convx_k<<<Mtot * Dm / 4 / 256, 256>>>(x, xf);
    convw_k<<<dim3(32, 32, 4), dim3(32, 8)>>>(WQ, WK, WV, WO, wf);

    qkv_gemm<<<dim3(3 * Dm / 128, Mtot / 128), 128, GSMEM>>>(
        xf, wf, qf, kf, vf);

    attn_mma<<<dim3(Sq / 128, Hh, Bq), 256, ASMEM>>>(qf, kf, vf, ah);

    wo_gemm<<<dim3(Dm / 128, Mtot / 128), 128, GSMEM>>>(
        ah, wf + 3 * (size_t)Dm * Dm, out);
}